// round 1
// baseline (speedup 1.0000x reference)
#include <cuda_runtime.h>
#include <cuda_bf16.h>

// Light_PAM on GB300.
// Structure: stage1 PAM is out = alpha1*fe + x. In the benchmark inputs
// alpha1 == 0 exactly, so stage1 is the identity and the whole problem is
// 2048 independent PAMs over 8x8 tiles (C=256, L=64).
// We keep a generic fallback for alpha1 != 0 (device-side branch), which
// writes its result into a __device__ scratch buffer g_y; the main stage2
// kernel then reads from g_y instead of x.

#define CC   256
#define LL   64
#define C8   32

// ---------------- scratch for the (unexercised in bench) generic path ----
__device__ float g_y [8L*256*128*128];      // stage1 output, x-layout (128 MiB)
__device__ float g_fb[512L*32*256];
__device__ float g_fc[512L*32*256];
__device__ float g_fd[512L*256*256];
__device__ float g_at[512L*256*256];

// ---------------- generic stage-1 fallback (runs only if alpha1 != 0) ----
__global__ void pam1_fallback(const float* __restrict__ x,
                              const float* __restrict__ Wb, const float* __restrict__ bb,
                              const float* __restrict__ Wc, const float* __restrict__ bc,
                              const float* __restrict__ Wd, const float* __restrict__ bd,
                              const float* __restrict__ alpha1p)
{
    const float alpha1 = alpha1p[0];
    if (alpha1 == 0.0f) return;   // identity: stage2 reads x directly

    const int b  = blockIdx.x;          // b = (n*8+ph)*8+pw
    const int n  = b >> 6;
    const int ph = (b >> 3) & 7;
    const int pw = b & 7;

    auto gx = [&](int c, int l) -> float {
        int qh = l >> 4, qw = l & 15;
        return x[(((long)n*256 + c)*128 + qh*8 + ph)*128 + qw*8 + pw];
    };

    // fb, fc  [32, 256]
    for (int idx = threadIdx.x; idx < 32*256; idx += blockDim.x) {
        int o = idx >> 8, l = idx & 255;
        float ab = bb[o], ac = bc[o];
        for (int c = 0; c < 256; c++) {
            float xv = gx(c, l);
            ab += Wb[o*256 + c] * xv;
            ac += Wc[o*256 + c] * xv;
        }
        g_fb[(long)b*8192 + idx] = ab;
        g_fc[(long)b*8192 + idx] = ac;
    }
    __syncthreads();

    // fd [256, 256]
    for (int idx = threadIdx.x; idx < 256*256; idx += blockDim.x) {
        int c = idx >> 8, m = idx & 255;
        float a = bd[c];
        for (int k = 0; k < 256; k++) a += Wd[c*256 + k] * gx(k, m);
        g_fd[(long)b*65536 + idx] = a;
    }
    __syncthreads();

    // attn rows (one thread per row)
    if (threadIdx.x < 256) {
        int l = threadIdx.x;
        const float* fb_ = g_fb + (long)b*8192;
        const float* fc_ = g_fc + (long)b*8192;
        float mx = -1e30f;
        for (int m = 0; m < 256; m++) {
            float s = 0.f;
            for (int o = 0; o < 32; o++) s += fb_[o*256 + l] * fc_[o*256 + m];
            if (s > mx) mx = s;
        }
        float* ar = g_at + (long)b*65536 + (long)l*256;
        float sum = 0.f;
        for (int m = 0; m < 256; m++) {
            float s = 0.f;
            for (int o = 0; o < 32; o++) s += fb_[o*256 + l] * fc_[o*256 + m];
            float p = __expf(s - mx);
            ar[m] = p; sum += p;
        }
        float inv = 1.0f / sum;
        for (int m = 0; m < 256; m++) ar[m] *= inv;
    }
    __syncthreads();

    // fe + residual -> g_y
    for (int idx = threadIdx.x; idx < 256*256; idx += blockDim.x) {
        int c = idx >> 8, l = idx & 255;
        const float* fd_ = g_fd + (long)b*65536 + (long)c*256;
        const float* ar  = g_at + (long)b*65536 + (long)l*256;
        float a = 0.f;
        for (int m = 0; m < 256; m++) a += fd_[m] * ar[m];
        int qh = l >> 4, qw = l & 15;
        g_y[(((long)n*256 + c)*128 + qh*8 + ph)*128 + qw*8 + pw] = alpha1*a + gx(c, l);
    }
}

// ---------------- main stage-2 kernel: one CTA per 8x8 tile ----------------
// SMEM layout (floats):
//   Xs   [256*64]      X tile            65536 B
//   fbs  [32*64]                          8192 B
//   fcs  [32*64]                          8192 B
//   Sa   [64*65]       attn (padded)     16640 B
//   frow [8*4*64]      per-warp fd rows   8192 B
// total 106752 B -> 2 CTAs/SM (213.5 KB of 228 KB)
#define SMEM_FLOATS (CC*LL + C8*LL + C8*LL + 64*65 + 8*4*64)
#define SMEM_BYTES  (SMEM_FLOATS * 4)

__global__ __launch_bounds__(256, 2)
void pam2_kernel(const float* __restrict__ x,
                 const float* __restrict__ Wb, const float* __restrict__ bb,
                 const float* __restrict__ Wc, const float* __restrict__ bc,
                 const float* __restrict__ Wd, const float* __restrict__ bd,
                 const float* __restrict__ alpha1p, const float* __restrict__ alpha2p,
                 float* __restrict__ out)
{
    extern __shared__ float sm[];
    float* Xs   = sm;                    // [256][64]
    float* fbs  = Xs  + CC*LL;           // [32][64]
    float* fcs  = fbs + C8*LL;           // [32][64]
    float* Sa   = fcs + C8*LL;           // [64][65]
    float* frow = Sa  + 64*65;           // [8 warps][4][64]

    const int b    = blockIdx.x;         // b = (n*16+qh)*16+qw
    const int n    = b >> 8;
    const int qh   = (b >> 4) & 15;
    const int qw   = b & 15;
    const int t    = threadIdx.x;
    const int wid  = t >> 5;
    const int lane = t & 31;

    const float alpha1 = alpha1p[0];
    const float alpha  = alpha2p[0];
    const float* src = (alpha1 == 0.0f) ? x : g_y;

    // element (c, ph, pw) lives at src[tile_base + c*16384 + ph*128 + pw]
    const long tile_base = (long)n*256*16384 + (long)(qh*8)*128 + (qw*8);

    // ---- load X tile (float4, fully coalesced) ----
    for (int idx = t; idx < 2048; idx += 256) {
        int c = idx >> 3, ph = idx & 7;
        const float4* p = (const float4*)(src + tile_base + (long)c*16384 + ph*128);
        float4 a = p[0], bq = p[1];
        float* dst = Xs + c*64 + ph*8;
        dst[0]=a.x;  dst[1]=a.y;  dst[2]=a.z;  dst[3]=a.w;
        dst[4]=bq.x; dst[5]=bq.y; dst[6]=bq.z; dst[7]=bq.w;
    }
    __syncthreads();

    // ---- fb, fc: warp 'wid' owns rows o0..o0+3, lane owns l and l+32 ----
    {
        const int o0 = wid * 4;
        const int l0 = lane, l1 = lane + 32;
        const float4* Wb4 = (const float4*)Wb;
        const float4* Wc4 = (const float4*)Wc;
        float ab[4][2], ac[4][2];
        #pragma unroll
        for (int j = 0; j < 4; j++) {
            ab[j][0] = ab[j][1] = bb[o0+j];
            ac[j][0] = ac[j][1] = bc[o0+j];
        }
        for (int k4 = 0; k4 < 64; k4++) {
            float4 wbv[4], wcv[4];
            #pragma unroll
            for (int j = 0; j < 4; j++) {
                wbv[j] = __ldg(&Wb4[(o0+j)*64 + k4]);
                wcv[j] = __ldg(&Wc4[(o0+j)*64 + k4]);
            }
            #pragma unroll
            for (int kk = 0; kk < 4; kk++) {
                int k = k4*4 + kk;
                float x0 = Xs[k*64 + l0], x1 = Xs[k*64 + l1];
                #pragma unroll
                for (int j = 0; j < 4; j++) {
                    float wbe = ((const float*)&wbv[j])[kk];
                    float wce = ((const float*)&wcv[j])[kk];
                    ab[j][0] += wbe*x0; ab[j][1] += wbe*x1;
                    ac[j][0] += wce*x0; ac[j][1] += wce*x1;
                }
            }
        }
        #pragma unroll
        for (int j = 0; j < 4; j++) {
            fbs[(o0+j)*64 + l0] = ab[j][0]; fbs[(o0+j)*64 + l1] = ab[j][1];
            fcs[(o0+j)*64 + l0] = ac[j][0]; fcs[(o0+j)*64 + l1] = ac[j][1];
        }
    }
    __syncthreads();

    // ---- S = fb^T fc and row softmax; warp owns 8 rows ----
    {
        for (int r = 0; r < 8; r++) {
            int l = wid*8 + r;
            float s0 = 0.f, s1 = 0.f;
            #pragma unroll
            for (int o = 0; o < 32; o++) {
                float fv = fbs[o*64 + l];           // broadcast
                s0 += fv * fcs[o*64 + lane];
                s1 += fv * fcs[o*64 + lane + 32];
            }
            float mx = fmaxf(s0, s1);
            #pragma unroll
            for (int off = 16; off; off >>= 1)
                mx = fmaxf(mx, __shfl_xor_sync(0xffffffffu, mx, off));
            float p0 = __expf(s0 - mx), p1 = __expf(s1 - mx);
            float sum = p0 + p1;
            #pragma unroll
            for (int off = 16; off; off >>= 1)
                sum += __shfl_xor_sync(0xffffffffu, sum, off);
            float inv = 1.0f / sum;
            Sa[l*65 + lane]      = p0 * inv;
            Sa[l*65 + lane + 32] = p1 * inv;
        }
    }
    __syncthreads();

    // ---- fd + fe + residual: warp owns 32 c-rows, 4 at a time ----
    {
        float* myfrow = frow + wid*4*64;
        const float4* Wd4 = (const float4*)Wd;
        const int ph0 = lane >> 3,        pw0 = lane & 7;
        const int ph1 = (lane + 32) >> 3, pw1 = (lane + 32) & 7;

        for (int cg = 0; cg < 8; cg++) {
            const int c0 = wid*32 + cg*4;
            float f[4][2];
            #pragma unroll
            for (int j = 0; j < 4; j++) f[j][0] = f[j][1] = bd[c0+j];

            for (int k4 = 0; k4 < 64; k4++) {
                float4 wv[4];
                #pragma unroll
                for (int j = 0; j < 4; j++) wv[j] = __ldg(&Wd4[(c0+j)*64 + k4]);
                #pragma unroll
                for (int kk = 0; kk < 4; kk++) {
                    int k = k4*4 + kk;
                    float x0 = Xs[k*64 + lane], x1 = Xs[k*64 + lane + 32];
                    #pragma unroll
                    for (int j = 0; j < 4; j++) {
                        float we = ((const float*)&wv[j])[kk];
                        f[j][0] += we*x0; f[j][1] += we*x1;
                    }
                }
            }
            #pragma unroll
            for (int j = 0; j < 4; j++) {
                myfrow[j*64 + lane]      = f[j][0];
                myfrow[j*64 + lane + 32] = f[j][1];
            }
            __syncwarp();

            float e[4][2];
            #pragma unroll
            for (int j = 0; j < 4; j++) e[j][0] = e[j][1] = 0.f;
            #pragma unroll 4
            for (int m = 0; m < 64; m++) {
                float a0 = Sa[lane*65 + m];            // stride 65: conflict-free
                float a1 = Sa[(lane+32)*65 + m];
                #pragma unroll
                for (int j = 0; j < 4; j++) {
                    float fv = myfrow[j*64 + m];       // broadcast
                    e[j][0] += fv*a0; e[j][1] += fv*a1;
                }
            }
            #pragma unroll
            for (int j = 0; j < 4; j++) {
                const int c = c0 + j;
                const long obase = tile_base + (long)c*16384;
                out[obase + ph0*128 + pw0] = alpha*e[j][0] + Xs[c*64 + lane];
                out[obase + ph1*128 + pw1] = alpha*e[j][1] + Xs[c*64 + lane + 32];
            }
            __syncwarp();   // protect myfrow before next cg overwrites it
        }
    }
}

// ---------------- launch ----------------
extern "C" void kernel_launch(void* const* d_in, const int* in_sizes, int n_in,
                              void* d_out, int out_size)
{
    const float* x      = (const float*)d_in[0];
    const float* Wb1    = (const float*)d_in[1];
    const float* bb1    = (const float*)d_in[2];
    const float* Wc1    = (const float*)d_in[3];
    const float* bc1    = (const float*)d_in[4];
    const float* Wd1    = (const float*)d_in[5];
    const float* bd1    = (const float*)d_in[6];
    const float* alpha1 = (const float*)d_in[7];
    const float* Wb2    = (const float*)d_in[8];
    const float* bb2    = (const float*)d_in[9];
    const float* Wc2    = (const float*)d_in[10];
    const float* bc2    = (const float*)d_in[11];
    const float* Wd2    = (const float*)d_in[12];
    const float* bd2    = (const float*)d_in[13];
    const float* alpha2 = (const float*)d_in[14];
    float* out = (float*)d_out;

    cudaFuncSetAttribute(pam2_kernel,
                         cudaFuncAttributeMaxDynamicSharedMemorySize, SMEM_BYTES);

    // Generic stage-1 (no-op when alpha1 == 0, which is the benchmark case).
    pam1_fallback<<<512, 256>>>(x, Wb1, bb1, Wc1, bc1, Wd1, bd1, alpha1);

    // Stage-2 PAM over 2048 8x8 tiles; reads x directly when alpha1 == 0.
    pam2_kernel<<<2048, 256, SMEM_BYTES>>>(x, Wb2, bb2, Wc2, bc2, Wd2, bd2,
                                           alpha1, alpha2, out);
}

// round 3
// speedup vs baseline: 2.5737x; 2.5737x over previous
#include <cuda_runtime.h>
#include <cuda_bf16.h>
#include <mma.h>
#include <cstdint>

using namespace nvcuda;

// ===================== Light_PAM, wmma (HMMA bf16) version =====================
// alpha1 == 0 in the benchmark -> stage1 is identity; problem = 2048
// independent PAMs over 8x8 tiles (C=256, L=64). One CTA per tile, all four
// GEMMs on tensor cores via wmma 16x16x16 bf16. Weights streamed as bf16 from
// global (L1-resident, reused across CTAs on the same SM).

typedef __nv_bfloat16 bf16;

// ---------------- prepared bf16 weights (natural row-major) ----------------
__device__ bf16 g_Wbc[64 * 256];     // rows 0-31 Wb, rows 32-63 Wc
__device__ bf16 g_Wd [256 * 256];

__global__ void prep_weights(const float* __restrict__ Wb, const float* __restrict__ Wc,
                             const float* __restrict__ Wd){
    int i = blockIdx.x * 256 + threadIdx.x;
    if (i < 8192)                    g_Wbc[i] = __float2bfloat16(Wb[i]);
    else if (i < 16384)              g_Wbc[i] = __float2bfloat16(Wc[i - 8192]);
    else if (i < 16384 + 65536)      g_Wd[i - 16384] = __float2bfloat16(Wd[i - 16384]);
}

// ---------------- scratch for the generic alpha1!=0 path ----------------
__device__ float g_y [8L*256*128*128];
__device__ float g_fb[512L*32*256];
__device__ float g_fc[512L*32*256];
__device__ float g_fd[512L*256*256];
__device__ float g_at[512L*256*256];

__global__ void pam1_fallback(const float* __restrict__ x,
                              const float* __restrict__ Wb, const float* __restrict__ bb,
                              const float* __restrict__ Wc, const float* __restrict__ bc,
                              const float* __restrict__ Wd, const float* __restrict__ bd,
                              const float* __restrict__ alpha1p)
{
    const float alpha1 = alpha1p[0];
    if (alpha1 == 0.0f) return;
    const int b  = blockIdx.x;
    const int n  = b >> 6;
    const int ph = (b >> 3) & 7;
    const int pw = b & 7;
    auto gx = [&](int c, int l) -> float {
        int qh = l >> 4, qw = l & 15;
        return x[(((long)n*256 + c)*128 + qh*8 + ph)*128 + qw*8 + pw];
    };
    for (int idx = threadIdx.x; idx < 32*256; idx += blockDim.x) {
        int o = idx >> 8, l = idx & 255;
        float ab = bb[o], ac = bc[o];
        for (int c = 0; c < 256; c++) {
            float xv = gx(c, l);
            ab += Wb[o*256 + c] * xv;
            ac += Wc[o*256 + c] * xv;
        }
        g_fb[(long)b*8192 + idx] = ab;
        g_fc[(long)b*8192 + idx] = ac;
    }
    __syncthreads();
    for (int idx = threadIdx.x; idx < 256*256; idx += blockDim.x) {
        int c = idx >> 8, m = idx & 255;
        float a = bd[c];
        for (int k = 0; k < 256; k++) a += Wd[c*256 + k] * gx(k, m);
        g_fd[(long)b*65536 + idx] = a;
    }
    __syncthreads();
    if (threadIdx.x < 256) {
        int l = threadIdx.x;
        const float* fb_ = g_fb + (long)b*8192;
        const float* fc_ = g_fc + (long)b*8192;
        float mx = -1e30f;
        for (int m = 0; m < 256; m++) {
            float s = 0.f;
            for (int o = 0; o < 32; o++) s += fb_[o*256 + l] * fc_[o*256 + m];
            if (s > mx) mx = s;
        }
        float* ar = g_at + (long)b*65536 + (long)l*256;
        float sum = 0.f;
        for (int m = 0; m < 256; m++) {
            float s = 0.f;
            for (int o = 0; o < 32; o++) s += fb_[o*256 + l] * fc_[o*256 + m];
            float p = __expf(s - mx);
            ar[m] = p; sum += p;
        }
        float inv = 1.0f / sum;
        for (int m = 0; m < 256; m++) ar[m] *= inv;
    }
    __syncthreads();
    for (int idx = threadIdx.x; idx < 256*256; idx += blockDim.x) {
        int c = idx >> 8, l = idx & 255;
        const float* fd_ = g_fd + (long)b*65536 + (long)c*256;
        const float* ar  = g_at + (long)b*65536 + (long)l*256;
        float a = 0.f;
        for (int m = 0; m < 256; m++) a += fd_[m] * ar[m];
        int qh = l >> 4, qw = l & 15;
        g_y[(((long)n*256 + c)*128 + qh*8 + ph)*128 + qw*8 + pw] = alpha1*a + gx(c, l);
    }
}

// ---------------- main kernel: one CTA per 8x8 tile ----------------
// SMEM layout (bytes):
//   Xs   bf16 [256][72]   36864   X tile, natural [c][l]
//   Fbc  bf16 [64][72]     9216   fb rows 0-31, fc rows 32-63, [o][l]
//   Sf   f32  [64][72]    18432   fb/fc C scratch, then S, then P bf16 alias
//   Fd   bf16 [64][72]     9216   fd chunk (bf16, bias added)
//   Fef  f32  [64][72]    18432   fd / fe float C scratch
#define LDH  72          // bf16/float leading dim (elements)
#define LDP  144         // P leading dim in bf16 elements (= 72 floats)
#define OFF_XS   0
#define OFF_FBC  36864
#define OFF_SF   46080
#define OFF_FD   64512
#define OFF_FEF  73728
#define SMEM_TOTAL 92160

__global__ __launch_bounds__(256, 2)
void pam2_wmma(const float* __restrict__ x,
               const float* __restrict__ bb, const float* __restrict__ bc,
               const float* __restrict__ bd,
               const float* __restrict__ alpha1p, const float* __restrict__ alpha2p,
               float* __restrict__ out)
{
    extern __shared__ __align__(16) char smem[];
    bf16*  Xs  = (bf16*) (smem + OFF_XS);
    bf16*  Fbc = (bf16*) (smem + OFF_FBC);
    float* Sf  = (float*)(smem + OFF_SF);
    bf16*  Pm  = (bf16*) (smem + OFF_SF);    // alias: P[l][m], ld=LDP
    bf16*  Fd  = (bf16*) (smem + OFF_FD);
    float* Fef = (float*)(smem + OFF_FEF);

    const int t = threadIdx.x, wid = t >> 5, lane = t & 31;
    const int tile = blockIdx.x;
    const int n = tile >> 8, qh = (tile >> 4) & 15, qw = tile & 15;
    const long tb = (long)n * 256 * 16384 + (long)(qh * 8) * 128 + qw * 8;

    const float alpha1 = alpha1p[0];
    const float alpha  = alpha2p[0];
    const float* src = (alpha1 == 0.0f) ? x : g_y;

    // warp tile assignment for [64][64] C grids: warp owns 2 adjacent col tiles
    const int tr = wid >> 1;             // C row-tile (0..3)
    const int tc = (wid & 1) * 2;        // C col-tile base (0 or 2)

    // ---- Phase 0: load X tile -> Xs[c][l] bf16 ----
    for (int idx = t; idx < 2048; idx += 256) {
        const int c = idx >> 3, ph = idx & 7;
        const float4* p = (const float4*)(src + tb + ((long)c << 14) + (ph << 7));
        float4 a = p[0], b4 = p[1];
        __nv_bfloat162 v0 = __floats2bfloat162_rn(a.x, a.y);
        __nv_bfloat162 v1 = __floats2bfloat162_rn(a.z, a.w);
        __nv_bfloat162 v2 = __floats2bfloat162_rn(b4.x, b4.y);
        __nv_bfloat162 v3 = __floats2bfloat162_rn(b4.z, b4.w);
        uint4 pk; pk.x = *(uint32_t*)&v0; pk.y = *(uint32_t*)&v1;
        pk.z = *(uint32_t*)&v2; pk.w = *(uint32_t*)&v3;
        *(uint4*)(Xs + c * LDH + ph * 8) = pk;
    }
    __syncthreads();

    // ---- Phase 1: [fb;fc] = Wbc @ X  -> Sf (float) ----
    {
        wmma::fragment<wmma::accumulator, 16, 16, 16, float> C0, C1;
        wmma::fill_fragment(C0, 0.0f); wmma::fill_fragment(C1, 0.0f);
        #pragma unroll
        for (int k = 0; k < 16; k++) {
            wmma::fragment<wmma::matrix_a, 16, 16, 16, bf16, wmma::row_major> A;
            wmma::fragment<wmma::matrix_b, 16, 16, 16, bf16, wmma::row_major> B0, B1;
            wmma::load_matrix_sync(A, g_Wbc + (tr * 16) * 256 + k * 16, 256);
            wmma::load_matrix_sync(B0, Xs + (k * 16) * LDH + tc * 16, LDH);
            wmma::load_matrix_sync(B1, Xs + (k * 16) * LDH + tc * 16 + 16, LDH);
            wmma::mma_sync(C0, A, B0, C0);
            wmma::mma_sync(C1, A, B1, C1);
        }
        wmma::store_matrix_sync(Sf + (tr * 16) * LDH + tc * 16,      C0, LDH, wmma::mem_row_major);
        wmma::store_matrix_sync(Sf + (tr * 16) * LDH + tc * 16 + 16, C1, LDH, wmma::mem_row_major);
    }
    __syncthreads();

    // ---- Phase 2: bias + bf16 -> Fbc[o][l] ----
    for (int idx = t; idx < 4096; idx += 256) {
        const int o = idx >> 6, l = idx & 63;
        const float bias = (o < 32) ? bb[o] : bc[o - 32];
        Fbc[o * LDH + l] = __float2bfloat16(Sf[o * LDH + l] + bias);
    }
    __syncthreads();

    // ---- Phase 3: S[l][m] = fb^T fc  (K=32) -> Sf ----
    {
        wmma::fragment<wmma::accumulator, 16, 16, 16, float> C0, C1;
        wmma::fill_fragment(C0, 0.0f); wmma::fill_fragment(C1, 0.0f);
        #pragma unroll
        for (int k = 0; k < 2; k++) {
            wmma::fragment<wmma::matrix_a, 16, 16, 16, bf16, wmma::col_major> A;   // fb[o][l]
            wmma::fragment<wmma::matrix_b, 16, 16, 16, bf16, wmma::row_major> B0, B1; // fc[o][m]
            wmma::load_matrix_sync(A, Fbc + (k * 16) * LDH + tr * 16, LDH);
            wmma::load_matrix_sync(B0, Fbc + 32 * LDH + (k * 16) * LDH + tc * 16, LDH);
            wmma::load_matrix_sync(B1, Fbc + 32 * LDH + (k * 16) * LDH + tc * 16 + 16, LDH);
            wmma::mma_sync(C0, A, B0, C0);
            wmma::mma_sync(C1, A, B1, C1);
        }
        wmma::store_matrix_sync(Sf + (tr * 16) * LDH + tc * 16,      C0, LDH, wmma::mem_row_major);
        wmma::store_matrix_sync(Sf + (tr * 16) * LDH + tc * 16 + 16, C1, LDH, wmma::mem_row_major);
    }
    __syncthreads();

    // ---- Phase 4: row softmax -> P bf16 (aliased on Sf) ----
    for (int j = 0; j < 8; j++) {
        const int l = wid * 8 + j;
        float s0 = Sf[l * LDH + lane];
        float s1 = Sf[l * LDH + lane + 32];
        float mx = fmaxf(s0, s1);
        #pragma unroll
        for (int off = 16; off; off >>= 1)
            mx = fmaxf(mx, __shfl_xor_sync(0xffffffffu, mx, off));
        float p0 = __expf(s0 - mx), p1 = __expf(s1 - mx);
        float sum = p0 + p1;
        #pragma unroll
        for (int off = 16; off; off >>= 1)
            sum += __shfl_xor_sync(0xffffffffu, sum, off);
        const float inv = 1.0f / sum;
        Pm[l * LDP + lane]      = __float2bfloat16(p0 * inv);
        Pm[l * LDP + lane + 32] = __float2bfloat16(p1 * inv);
    }
    __syncthreads();

    // ---- Phase 5: 4 chunks of 64 channels: fd -> fe -> out ----
    for (int cc = 0; cc < 4; cc++) {
        const int c0 = cc * 64;

        // fd = Wd[c0:c0+64] @ X   -> Fef (float)
        {
            wmma::fragment<wmma::accumulator, 16, 16, 16, float> C0, C1;
            wmma::fill_fragment(C0, 0.0f); wmma::fill_fragment(C1, 0.0f);
            #pragma unroll
            for (int k = 0; k < 16; k++) {
                wmma::fragment<wmma::matrix_a, 16, 16, 16, bf16, wmma::row_major> A;
                wmma::fragment<wmma::matrix_b, 16, 16, 16, bf16, wmma::row_major> B0, B1;
                wmma::load_matrix_sync(A, g_Wd + (c0 + tr * 16) * 256 + k * 16, 256);
                wmma::load_matrix_sync(B0, Xs + (k * 16) * LDH + tc * 16, LDH);
                wmma::load_matrix_sync(B1, Xs + (k * 16) * LDH + tc * 16 + 16, LDH);
                wmma::mma_sync(C0, A, B0, C0);
                wmma::mma_sync(C1, A, B1, C1);
            }
            wmma::store_matrix_sync(Fef + (tr * 16) * LDH + tc * 16,      C0, LDH, wmma::mem_row_major);
            wmma::store_matrix_sync(Fef + (tr * 16) * LDH + tc * 16 + 16, C1, LDH, wmma::mem_row_major);
        }
        __syncthreads();

        // bias + bf16 -> Fd[c][m]
        for (int idx = t; idx < 4096; idx += 256) {
            const int c = idx >> 6, m = idx & 63;
            Fd[c * LDH + m] = __float2bfloat16(Fef[c * LDH + m] + bd[c0 + c]);
        }
        __syncthreads();

        // fe = Fd @ P^T   (K=64) -> Fef (float)
        {
            wmma::fragment<wmma::accumulator, 16, 16, 16, float> C0, C1;
            wmma::fill_fragment(C0, 0.0f); wmma::fill_fragment(C1, 0.0f);
            #pragma unroll
            for (int k = 0; k < 4; k++) {
                wmma::fragment<wmma::matrix_a, 16, 16, 16, bf16, wmma::row_major> A;
                wmma::fragment<wmma::matrix_b, 16, 16, 16, bf16, wmma::col_major> B0, B1; // P[l][m]
                wmma::load_matrix_sync(A, Fd + (tr * 16) * LDH + k * 16, LDH);
                wmma::load_matrix_sync(B0, Pm + (tc * 16) * LDP + k * 16, LDP);
                wmma::load_matrix_sync(B1, Pm + (tc * 16 + 16) * LDP + k * 16, LDP);
                wmma::mma_sync(C0, A, B0, C0);
                wmma::mma_sync(C1, A, B1, C1);
            }
            wmma::store_matrix_sync(Fef + (tr * 16) * LDH + tc * 16,      C0, LDH, wmma::mem_row_major);
            wmma::store_matrix_sync(Fef + (tr * 16) * LDH + tc * 16 + 16, C1, LDH, wmma::mem_row_major);
        }
        __syncthreads();

        // epilogue: out = alpha*fe + x  (32B-sector aligned)
        for (int idx = t; idx < 512; idx += 256) {
            const int c = idx >> 3, ph = idx & 7;
            const long gb = tb + ((long)(c0 + c) << 14) + (ph << 7);
            float4 a0 = *(const float4*)(src + gb);
            float4 a1 = *(const float4*)(src + gb + 4);
            float4 f0 = *(const float4*)(Fef + c * LDH + ph * 8);
            float4 f1 = *(const float4*)(Fef + c * LDH + ph * 8 + 4);
            float4 o0, o1;
            o0.x = fmaf(alpha, f0.x, a0.x); o0.y = fmaf(alpha, f0.y, a0.y);
            o0.z = fmaf(alpha, f0.z, a0.z); o0.w = fmaf(alpha, f0.w, a0.w);
            o1.x = fmaf(alpha, f1.x, a1.x); o1.y = fmaf(alpha, f1.y, a1.y);
            o1.z = fmaf(alpha, f1.z, a1.z); o1.w = fmaf(alpha, f1.w, a1.w);
            *(float4*)(out + gb)     = o0;
            *(float4*)(out + gb + 4) = o1;
        }
        __syncthreads();   // protect Fef before next chunk's fd store
    }
}

// ---------------- launch ----------------
extern "C" void kernel_launch(void* const* d_in, const int* in_sizes, int n_in,
                              void* d_out, int out_size)
{
    const float* x      = (const float*)d_in[0];
    const float* Wb1    = (const float*)d_in[1];
    const float* bb1    = (const float*)d_in[2];
    const float* Wc1    = (const float*)d_in[3];
    const float* bc1    = (const float*)d_in[4];
    const float* Wd1    = (const float*)d_in[5];
    const float* bd1    = (const float*)d_in[6];
    const float* alpha1 = (const float*)d_in[7];
    const float* Wb2    = (const float*)d_in[8];
    const float* bb2    = (const float*)d_in[9];
    const float* Wc2    = (const float*)d_in[10];
    const float* bc2    = (const float*)d_in[11];
    const float* Wd2    = (const float*)d_in[12];
    const float* bd2    = (const float*)d_in[13];
    const float* alpha2 = (const float*)d_in[14];
    float* out = (float*)d_out;

    prep_weights<<<320, 256>>>(Wb2, Wc2, Wd2);
    pam1_fallback<<<512, 256>>>(x, Wb1, bb1, Wc1, bc1, Wd1, bd1, alpha1);

    cudaFuncSetAttribute(pam2_wmma, cudaFuncAttributeMaxDynamicSharedMemorySize, SMEM_TOTAL);
    pam2_wmma<<<2048, 256, SMEM_TOTAL>>>(x, bb2, bc2, bd2, alpha1, alpha2, out);
}